// round 1
// baseline (speedup 1.0000x reference)
#include <cuda_runtime.h>
#include <math.h>

// Input order (metadata.txt / setup_inputs):
// 0: x        [1024, 2560] f32
// 1: h        [1024, 2560, 16] f32
// 2: W_dt_low [160, 2560] f32
// 3: W_dt     [2560, 160] f32
// 4: b_dt     [2560] f32
// 5: W_B      [16, 2560] f32
// 6: W_C      [16, 2560] f32
// 7: A_log    [2560, 16] f32
// 8: D        [2560] f32
// out: y      [1024, 2560] f32

#define B_SZ    1024
#define DIN     2560
#define DST     16
#define DTR     160
#define NPROJ   192      // 160 (dt_low) + 16 (Bt) + 16 (Ct)
#define SPLITK  8
#define KSPLIT  (DIN / SPLITK)   // 320

// ---------------- device scratch (no allocs allowed) ----------------
__device__ __align__(16) float g_Wc[NPROJ * DIN];                 // packed weights
__device__ __align__(16) float g_partial[SPLITK * B_SZ * NPROJ];  // split-K partials
__device__ __align__(16) float g_proj[B_SZ * NPROJ];              // dt_low | Bt | Ct
__device__ __align__(16) float g_dt[B_SZ * DIN];                  // softplus(dt)
__device__ __align__(16) float g_A2[DIN * DST];                   // -exp(A_log)

// ---------------- pack W_dt_low / W_B / W_C into one [192,2560] ----------------
__global__ void pack_w_kernel(const float* __restrict__ wdtlow,
                              const float* __restrict__ wb,
                              const float* __restrict__ wc) {
    int i = blockIdx.x * blockDim.x + threadIdx.x;       // float4 index
    int total4 = NPROJ * DIN / 4;
    if (i >= total4) return;
    int e = i * 4;
    int n = e / DIN;
    int k = e - n * DIN;
    const float* src;
    if (n < DTR)            src = wdtlow + (size_t)n * DIN + k;
    else if (n < DTR + DST) src = wb + (size_t)(n - DTR) * DIN + k;
    else                    src = wc + (size_t)(n - DTR - DST) * DIN + k;
    reinterpret_cast<float4*>(g_Wc)[i] = *reinterpret_cast<const float4*>(src);
}

// ---------------- A2 = -exp(A_log) ----------------
__global__ void prep_a_kernel(const float* __restrict__ a_log) {
    int i = blockIdx.x * blockDim.x + threadIdx.x;
    if (i < DIN * DST) g_A2[i] = -__expf(a_log[i]);
}

// ---------------- GEMM1 (split-K): partial[z] += x[64,320] @ Wc[64,320]^T ----------------
// C[m,n] = sum_k x[m,k] * Wc[n,k].  Tiles 64x64, BK=16, 256 thr, 4x4 microtile.
__global__ __launch_bounds__(256) void gemm1_kernel(const float* __restrict__ x) {
    __shared__ float As[16][68];
    __shared__ float Bs[16][68];
    const int tid = threadIdx.x;
    const int mBase = blockIdx.x * 64;
    const int nBase = blockIdx.y * 64;
    const int k0 = blockIdx.z * KSPLIT;
    const int tm = tid >> 4;            // 0..15
    const int tn = tid & 15;            // 0..15
    const int lr = tid >> 2;            // 0..63 load row
    const int lk = (tid & 3) * 4;       // 0,4,8,12

    float c[4][4] = {};
    const float* aptr = x    + (size_t)(mBase + lr) * DIN + k0 + lk;
    const float* bptr = g_Wc + (size_t)(nBase + lr) * DIN + k0 + lk;

    for (int kt = 0; kt < KSPLIT; kt += 16) {
        float4 av = *reinterpret_cast<const float4*>(aptr + kt);
        float4 bv = *reinterpret_cast<const float4*>(bptr + kt);
        As[lk + 0][lr] = av.x; As[lk + 1][lr] = av.y;
        As[lk + 2][lr] = av.z; As[lk + 3][lr] = av.w;
        Bs[lk + 0][lr] = bv.x; Bs[lk + 1][lr] = bv.y;
        Bs[lk + 2][lr] = bv.z; Bs[lk + 3][lr] = bv.w;
        __syncthreads();
#pragma unroll
        for (int kk = 0; kk < 16; kk++) {
            float4 a = *reinterpret_cast<const float4*>(&As[kk][tm * 4]);
            float4 b = *reinterpret_cast<const float4*>(&Bs[kk][tn * 4]);
            c[0][0] = fmaf(a.x, b.x, c[0][0]); c[0][1] = fmaf(a.x, b.y, c[0][1]);
            c[0][2] = fmaf(a.x, b.z, c[0][2]); c[0][3] = fmaf(a.x, b.w, c[0][3]);
            c[1][0] = fmaf(a.y, b.x, c[1][0]); c[1][1] = fmaf(a.y, b.y, c[1][1]);
            c[1][2] = fmaf(a.y, b.z, c[1][2]); c[1][3] = fmaf(a.y, b.w, c[1][3]);
            c[2][0] = fmaf(a.z, b.x, c[2][0]); c[2][1] = fmaf(a.z, b.y, c[2][1]);
            c[2][2] = fmaf(a.z, b.z, c[2][2]); c[2][3] = fmaf(a.z, b.w, c[2][3]);
            c[3][0] = fmaf(a.w, b.x, c[3][0]); c[3][1] = fmaf(a.w, b.y, c[3][1]);
            c[3][2] = fmaf(a.w, b.z, c[3][2]); c[3][3] = fmaf(a.w, b.w, c[3][3]);
        }
        __syncthreads();
    }
    float* out = g_partial + ((size_t)blockIdx.z * B_SZ + mBase) * NPROJ + nBase;
#pragma unroll
    for (int i = 0; i < 4; i++) {
        float4 v = make_float4(c[i][0], c[i][1], c[i][2], c[i][3]);
        *reinterpret_cast<float4*>(out + (size_t)(tm * 4 + i) * NPROJ + tn * 4) = v;
    }
}

// ---------------- split-K reduce: proj = sum_z partial[z] ----------------
__global__ void reduce_kernel() {
    int i = blockIdx.x * blockDim.x + threadIdx.x;     // float4 index
    const int total4 = B_SZ * NPROJ / 4;
    if (i >= total4) return;
    const float4* p = reinterpret_cast<const float4*>(g_partial);
    float4 s = p[i];
#pragma unroll
    for (int z = 1; z < SPLITK; z++) {
        float4 v = p[(size_t)z * total4 + i];
        s.x += v.x; s.y += v.y; s.z += v.z; s.w += v.w;
    }
    reinterpret_cast<float4*>(g_proj)[i] = s;
}

// ---------------- GEMM2 + softplus: dt[b,n] = sp( proj[b,0:160] . W_dt[n,:] + b_dt[n] ) ----------------
__global__ __launch_bounds__(256) void gemm2_kernel(const float* __restrict__ wdt,
                                                    const float* __restrict__ bdt) {
    __shared__ float As[16][68];
    __shared__ float Bs[16][68];
    const int tid = threadIdx.x;
    const int mBase = blockIdx.x * 64;
    const int nBase = blockIdx.y * 64;
    const int tm = tid >> 4;
    const int tn = tid & 15;
    const int lr = tid >> 2;
    const int lk = (tid & 3) * 4;

    float c[4][4] = {};
    const float* aptr = g_proj + (size_t)(mBase + lr) * NPROJ + lk;
    const float* bptr = wdt    + (size_t)(nBase + lr) * DTR + lk;

    for (int kt = 0; kt < DTR; kt += 16) {
        float4 av = *reinterpret_cast<const float4*>(aptr + kt);
        float4 bv = *reinterpret_cast<const float4*>(bptr + kt);
        As[lk + 0][lr] = av.x; As[lk + 1][lr] = av.y;
        As[lk + 2][lr] = av.z; As[lk + 3][lr] = av.w;
        Bs[lk + 0][lr] = bv.x; Bs[lk + 1][lr] = bv.y;
        Bs[lk + 2][lr] = bv.z; Bs[lk + 3][lr] = bv.w;
        __syncthreads();
#pragma unroll
        for (int kk = 0; kk < 16; kk++) {
            float4 a = *reinterpret_cast<const float4*>(&As[kk][tm * 4]);
            float4 b = *reinterpret_cast<const float4*>(&Bs[kk][tn * 4]);
            c[0][0] = fmaf(a.x, b.x, c[0][0]); c[0][1] = fmaf(a.x, b.y, c[0][1]);
            c[0][2] = fmaf(a.x, b.z, c[0][2]); c[0][3] = fmaf(a.x, b.w, c[0][3]);
            c[1][0] = fmaf(a.y, b.x, c[1][0]); c[1][1] = fmaf(a.y, b.y, c[1][1]);
            c[1][2] = fmaf(a.y, b.z, c[1][2]); c[1][3] = fmaf(a.y, b.w, c[1][3]);
            c[2][0] = fmaf(a.z, b.x, c[2][0]); c[2][1] = fmaf(a.z, b.y, c[2][1]);
            c[2][2] = fmaf(a.z, b.z, c[2][2]); c[2][3] = fmaf(a.z, b.w, c[2][3]);
            c[3][0] = fmaf(a.w, b.x, c[3][0]); c[3][1] = fmaf(a.w, b.y, c[3][1]);
            c[3][2] = fmaf(a.w, b.z, c[3][2]); c[3][3] = fmaf(a.w, b.w, c[3][3]);
        }
        __syncthreads();
    }
    const int gn = nBase + tn * 4;
    float4 bb = *reinterpret_cast<const float4*>(bdt + gn);
#pragma unroll
    for (int i = 0; i < 4; i++) {
        float z0 = c[i][0] + bb.x, z1 = c[i][1] + bb.y;
        float z2 = c[i][2] + bb.z, z3 = c[i][3] + bb.w;
        // stable softplus: max(z,0) + log1p(exp(-|z|))
        float4 v;
        v.x = fmaxf(z0, 0.f) + log1pf(__expf(-fabsf(z0)));
        v.y = fmaxf(z1, 0.f) + log1pf(__expf(-fabsf(z1)));
        v.z = fmaxf(z2, 0.f) + log1pf(__expf(-fabsf(z2)));
        v.w = fmaxf(z3, 0.f) + log1pf(__expf(-fabsf(z3)));
        *reinterpret_cast<float4*>(g_dt + (size_t)(mBase + tm * 4 + i) * DIN + gn) = v;
    }
}

// ---------------- elementwise SSM: 4 threads per (b,d), one n-quad each ----------------
__global__ __launch_bounds__(256) void ssm_kernel(const float* __restrict__ x,
                                                  const float* __restrict__ h,
                                                  const float* __restrict__ Dv,
                                                  float* __restrict__ y) {
    __shared__ float ys[64];
    const int b = blockIdx.y;
    const int dBase = blockIdx.x * 64;
    const int tid = threadIdx.x;
    const int l4 = tid & 3;
    const int d = dBase + (tid >> 2);
    const int pair = b * DIN + d;

    const float dt_v = g_dt[pair];
    const float x_v = x[pair];
    const float4 h4  = *reinterpret_cast<const float4*>(h + (size_t)pair * DST + l4 * 4);
    const float4 A4  = *reinterpret_cast<const float4*>(g_A2 + (size_t)d * DST + l4 * 4);
    const float4 Bt4 = *reinterpret_cast<const float4*>(g_proj + (size_t)b * NPROJ + DTR + l4 * 4);
    const float4 Ct4 = *reinterpret_cast<const float4*>(g_proj + (size_t)b * NPROJ + DTR + DST + l4 * 4);

    const float dx = dt_v * x_v;
    float acc;
    {
        float e0 = __expf(dt_v * A4.x);
        float e1 = __expf(dt_v * A4.y);
        float e2 = __expf(dt_v * A4.z);
        float e3 = __expf(dt_v * A4.w);
        float hn0 = fmaf(e0, h4.x, dx * Bt4.x);
        float hn1 = fmaf(e1, h4.y, dx * Bt4.y);
        float hn2 = fmaf(e2, h4.z, dx * Bt4.z);
        float hn3 = fmaf(e3, h4.w, dx * Bt4.w);
        acc = hn0 * Ct4.x;
        acc = fmaf(hn1, Ct4.y, acc);
        acc = fmaf(hn2, Ct4.z, acc);
        acc = fmaf(hn3, Ct4.w, acc);
    }
    acc += __shfl_xor_sync(0xffffffffu, acc, 1);
    acc += __shfl_xor_sync(0xffffffffu, acc, 2);
    if (l4 == 0) ys[tid >> 2] = fmaf(Dv[d], x_v, acc);
    __syncthreads();
    if (tid < 64) y[(size_t)b * DIN + dBase + tid] = ys[tid];
}

// ---------------- launch ----------------
extern "C" void kernel_launch(void* const* d_in, const int* in_sizes, int n_in,
                              void* d_out, int out_size) {
    const float* x       = (const float*)d_in[0];
    const float* h       = (const float*)d_in[1];
    const float* wdtlow  = (const float*)d_in[2];
    const float* wdt     = (const float*)d_in[3];
    const float* bdt     = (const float*)d_in[4];
    const float* wb      = (const float*)d_in[5];
    const float* wc      = (const float*)d_in[6];
    const float* alog    = (const float*)d_in[7];
    const float* Dv      = (const float*)d_in[8];
    float* y = (float*)d_out;

    pack_w_kernel<<<(NPROJ * DIN / 4 + 255) / 256, 256>>>(wdtlow, wb, wc);
    prep_a_kernel<<<(DIN * DST + 255) / 256, 256>>>(alog);
    gemm1_kernel<<<dim3(B_SZ / 64, NPROJ / 64, SPLITK), 256>>>(x);
    reduce_kernel<<<(B_SZ * NPROJ / 4 + 255) / 256, 256>>>();
    gemm2_kernel<<<dim3(B_SZ / 64, DIN / 64), 256>>>(wdt, bdt);
    ssm_kernel<<<dim3(DIN / 64, B_SZ), 256>>>(x, h, Dv, y);
}